// round 14
// baseline (speedup 1.0000x reference)
#include <cuda_runtime.h>
#include <math.h>

// FineMatchingModule — algebraically collapsed (verified R3-R13, rel_err ~1.5e-8):
// attention layers add only window-uniform shifts which the final softmax
// cancels. Per point:
//   corr[n] = sum_j s[j] * flat[n*256+j],  n = 0..24
// flat[25*ch + p] = channel-major-flattened zero-padded 5x5 window of
// target_features at the truncated coarse position; s = center pixel channel
// vector (= pixel 12). refined = pos + softmax(corr) @ offsets,
// offsets1d = linspace(-3,2,5).
//
// R14: halve the request count. 64-thread CTA = one point, float4 per thread
// (channels 4q..4q+3): 1600 LDG.128 per point instead of 3200 LDG.64 -> half
// the L1tex wavefront-queue traffic, and 2-warp CTAs double the independent
// scheduling units. Streaming 4-deep float4 buffer spreads issue through
// compute. Thread's 100 products (idx = 100q + 25k + p) cross <=1 token
// boundary (100 < 256) -> dual accumulators; static gather (t0=(256n+99)/100,
// t1=(256n+255)/100, pb[t0-1] for n>0). No atomics, no reduction shuffles.

#define B_ 4
#define K_ 1024
#define H_ 256
#define W_ 256
#define C_ 256

// float4-unit offset of pixel p from window base pointer
#define OFFP(p) (((p) / 5) * (W_ * (C_ / 4)) + ((p) % 5) * (C_ / 4))

// products of pixel p for this thread's 4 channels: i = 25k + p, k = 0..3
#define PROD(p, vv) do {                                                  \
    const float e0_ = (vv).x * s0[(p)];                                   \
    const float e1_ = (vv).y * s0[25 + (p)];                              \
    const float e2_ = (vv).z * s0[50 + (p)];                              \
    const float e3_ = (vv).w * s0[75 + (p)];                              \
    if ((p) < split)      a0 += e0_; else a1 += e0_;                      \
    if ((p) + 25 < split) a0 += e1_; else a1 += e1_;                      \
    if ((p) + 50 < split) a0 += e2_; else a1 += e2_;                      \
    if ((p) + 75 < split) a0 += e3_; else a1 += e3_;                      \
} while (0)

__device__ __forceinline__ float4 ldwin4(const float* __restrict__ fb,
                                         int r, int c, int p, int q)
{
    const int rr = r - 2 + p / 5, cc = c - 2 + p % 5;
    if (rr >= 0 && rr < H_ && cc >= 0 && cc < W_)
        return ((const float4*)(fb + ((size_t)rr * W_ + cc) * C_))[q];
    return make_float4(0.f, 0.f, 0.f, 0.f);
}

__global__ __launch_bounds__(64, 18)
void fine_match_kernel(const float* __restrict__ tf,
                       const float* __restrict__ pos,
                       float* __restrict__ out)
{
    __shared__ float s_sh[356];          // center vector + 100-entry wrap
    __shared__ float pa[64];
    __shared__ float pb[64];

    const int q  = threadIdx.x;          // owns channels 4q .. 4q+3
    const int pt = blockIdx.x;           // one point per CTA

    const float pr = pos[2 * pt + 0];
    const float pc = pos[2 * pt + 1];
    const int r = (int)pr, c = (int)pc;  // pos >= 0 -> trunc == astype(int32)
    const float* fb = tf + (size_t)(pt >> 10) * (H_ * W_ * C_);   // K = 1024

    const int sb    = (100 * q) & 255;
    const int split = 256 - sb;          // product index >= split -> token n0+1

    // pixel order excluding center (12): six batches of 4
    const int P[24] = { 0, 1, 2, 3,   4, 5, 6, 7,
                        8, 9,10,11,  13,14,15,16,
                       17,18,19,20,  21,22,23,24 };

    float a0 = 0.f, a1 = 0.f;
    const float* s0;
    float4 v12;
    float4 buf[4];

    const bool interior = (r >= 2) & (r <= H_ - 3) & (c >= 2) & (c <= W_ - 3);
    if (interior) {
        const float4* base =
            (const float4*)(fb + ((size_t)(r - 2) * W_ + (c - 2)) * C_) + q;
        v12 = base[OFFP(12)];                       // s source first
        #pragma unroll
        for (int j = 0; j < 4; ++j) buf[j] = base[OFFP(P[j])];

        *(float4*)&s_sh[4 * q] = v12;               // stage s
        if (q < 25) *(float4*)&s_sh[256 + 4 * q] = v12;   // wrap 256..355
        __syncthreads();
        s0 = &s_sh[sb];

        #pragma unroll
        for (int bt = 0; bt < 5; ++bt) {            // consume bt, load bt+1
            #pragma unroll
            for (int j = 0; j < 4; ++j) {
                const float4 v = buf[j];
                buf[j] = base[OFFP(P[4 * (bt + 1) + j])];
                PROD(P[4 * bt + j], v);
            }
        }
        PROD(12, v12);                              // center products
        #pragma unroll
        for (int j = 0; j < 4; ++j) PROD(P[20 + j], buf[j]);
    } else {
        // border path (~3% of points, CTA-uniform): same streaming shape
        v12 = ((const float4*)(fb + ((size_t)r * W_ + c) * C_))[q];  // center in-bounds
        #pragma unroll
        for (int j = 0; j < 4; ++j) buf[j] = ldwin4(fb, r, c, P[j], q);

        *(float4*)&s_sh[4 * q] = v12;
        if (q < 25) *(float4*)&s_sh[256 + 4 * q] = v12;
        __syncthreads();
        s0 = &s_sh[sb];

        #pragma unroll
        for (int bt = 0; bt < 5; ++bt) {
            #pragma unroll
            for (int j = 0; j < 4; ++j) {
                const float4 v = buf[j];
                buf[j] = ldwin4(fb, r, c, P[4 * (bt + 1) + j], q);
                PROD(P[4 * bt + j], v);
            }
        }
        PROD(12, v12);
        #pragma unroll
        for (int j = 0; j < 4; ++j) PROD(P[20 + j], buf[j]);
    }

    pa[q] = a0;                          // plain STS — no atomics
    pb[q] = a1;
    __syncthreads();

    // ---- warp 0: static gather + softmax + expected offset ----
    if (q < 32) {
        const int lane = q;
        float logit = -INFINITY;
        if (lane < 25) {
            const int n  = lane;
            const int t0 = (256 * n + 99)  / 100;   // first a0 contributor
            const int t1 = (256 * n + 255) / 100;   // last  a0 contributor
            float sum = (n > 0) ? pb[t0 - 1] : 0.0f;
            #pragma unroll 3
            for (int t = t0; t <= t1; ++t) sum += pa[t];   // 2-3 iters
            logit = sum;
        }
        float m = logit;
        #pragma unroll
        for (int o = 16; o > 0; o >>= 1)
            m = fmaxf(m, __shfl_xor_sync(0xffffffffu, m, o));
        float e = (lane < 25) ? __expf(logit - m) : 0.0f;
        float se = e;
        #pragma unroll
        for (int o = 16; o > 0; o >>= 1)
            se += __shfl_xor_sync(0xffffffffu, se, o);
        const float prb = e / se;        // 0 for lane >= 25

        // offsets: linspace(-3, 2, 5) = -3 + 1.25*k (exact fp32)
        const int ir = lane / 5;
        const int ic = lane - ir * 5;
        float dr = prb * (-3.0f + 1.25f * (float)ir);
        float dc = prb * (-3.0f + 1.25f * (float)ic);
        #pragma unroll
        for (int o = 16; o > 0; o >>= 1) {
            dr += __shfl_xor_sync(0xffffffffu, dr, o);
            dc += __shfl_xor_sync(0xffffffffu, dc, o);
        }
        if (lane == 0) {
            out[2 * pt + 0] = pr + dr;
            out[2 * pt + 1] = pc + dc;
        }
    }
}

extern "C" void kernel_launch(void* const* d_in, const int* in_sizes, int n_in,
                              void* d_out, int out_size)
{
    (void)in_sizes; (void)n_in; (void)out_size;
    // metadata order: 0=source_features (unused by reference), 1=target_features,
    // 2=coarse_positions, 3..6 = Wq,Wk,Wv,Wo (cancel algebraically)
    const float* tf  = (const float*)d_in[1];
    const float* pos = (const float*)d_in[2];
    float* out = (float*)d_out;

    fine_match_kernel<<<B_ * K_, 64>>>(tf, pos, out);
}

// round 15
// speedup vs baseline: 1.4081x; 1.4081x over previous
#include <cuda_runtime.h>
#include <math.h>

// FineMatchingModule — algebraically collapsed (verified R3-R14, rel_err ~1.5e-8):
// both attention layers add only window-uniform shifts which the final softmax
// cancels. Per point:
//   corr[n] = sum_j s[j] * flat[n*256+j],  n = 0..24
// flat[25*ch + p] = channel-major-flattened zero-padded 5x5 window of
// target_features at the truncated coarse position; s = center pixel channel
// vector (= pixel 12). refined = pos + softmax(corr) @ offsets,
// offsets1d = linspace(-3,2,5).
//
// R15 (final): exact champion configuration (R11, 16.9us) + __expf.
// Session conclusion: kernel is bound by the random-5KB-window DRAM gather
// ceiling (~4.6TB/s on the compulsory ~89MB unique footprint); occupancy,
// barrier structure, buffer depth, CTA grain, and access width were each
// varied independently and the 16.9-17.2us floor is invariant.
//   - 128-thread CTA = one point; ~10 CTAs/SM.
//   - streaming 4-deep float2 register buffer: 6 consume-batches, each
//     issuing the next batch's 4 LDGs (load issue spread through compute).
//   - one staging barrier; dual-accumulator static-token reduction
//     (no atomics, no reduction shuffles); warp-0 gather + softmax.

#define B_ 4
#define K_ 1024
#define H_ 256
#define W_ 256
#define C_ 256

// float2-unit offset of pixel p from window base pointer
#define OFFP(p) (((p) / 5) * (W_ * (C_ / 2)) + ((p) % 5) * (C_ / 2))

// products of pixel p for this thread's channels: idx = 50q + p (x), +25 (y)
#define PROD(p, vv) do {                                            \
    const float sx_ = s0[(p)];                                      \
    const float sy_ = s0[25 + (p)];                                 \
    if ((p) < split)      a0 = fmaf((vv).x, sx_, a0);               \
    else                  a1 = fmaf((vv).x, sx_, a1);               \
    if ((p) + 25 < split) a0 = fmaf((vv).y, sy_, a0);               \
    else                  a1 = fmaf((vv).y, sy_, a1);               \
} while (0)

__device__ __forceinline__ float2 ldwin(const float* __restrict__ fb,
                                        int r, int c, int p, int q)
{
    const int rr = r - 2 + p / 5, cc = c - 2 + p % 5;
    if (rr >= 0 && rr < H_ && cc >= 0 && cc < W_)
        return ((const float2*)(fb + ((size_t)rr * W_ + cc) * C_))[q];
    return make_float2(0.f, 0.f);
}

__global__ __launch_bounds__(128, 10)
void fine_match_kernel(const float* __restrict__ tf,
                       const float* __restrict__ pos,
                       float* __restrict__ out)
{
    __shared__ float s_sh[312];          // center vector + 50-entry wrap
    __shared__ float pa[128];
    __shared__ float pb[128];

    const int q  = threadIdx.x;          // owns channels 2q, 2q+1
    const int pt = blockIdx.x;           // one point per CTA

    const float pr = pos[2 * pt + 0];
    const float pc = pos[2 * pt + 1];
    const int r = (int)pr, c = (int)pc;  // pos >= 0 -> trunc == astype(int32)
    const float* fb = tf + (size_t)(pt >> 10) * (H_ * W_ * C_);   // K = 1024

    const int sb    = (50 * q) & 255;
    const int split = 256 - sb;          // product index >= split -> token n0+1

    // pixel order excluding center (12): six batches of 4
    const int P[24] = { 0, 1, 2, 3,   4, 5, 6, 7,
                        8, 9,10,11,  13,14,15,16,
                       17,18,19,20,  21,22,23,24 };

    float a0 = 0.f, a1 = 0.f;
    const float* s0;
    float2 v12;
    float2 buf[4];

    const bool interior = (r >= 2) & (r <= H_ - 3) & (c >= 2) & (c <= W_ - 3);
    if (interior) {
        const float2* base =
            (const float2*)(fb + ((size_t)(r - 2) * W_ + (c - 2)) * C_) + q;
        v12 = base[OFFP(12)];                       // s source first
        #pragma unroll
        for (int j = 0; j < 4; ++j) buf[j] = base[OFFP(P[j])];

        s_sh[2 * q]     = v12.x;                    // stage s (+wrap)
        s_sh[2 * q + 1] = v12.y;
        if (q < 25) {
            s_sh[256 + 2 * q]     = v12.x;
            s_sh[256 + 2 * q + 1] = v12.y;
        }
        __syncthreads();
        s0 = &s_sh[sb];

        #pragma unroll
        for (int bt = 0; bt < 5; ++bt) {            // consume bt, load bt+1
            #pragma unroll
            for (int j = 0; j < 4; ++j) {
                const float2 v = buf[j];
                buf[j] = base[OFFP(P[4 * (bt + 1) + j])];
                PROD(P[4 * bt + j], v);
            }
        }
        PROD(12, v12);                              // center products
        #pragma unroll
        for (int j = 0; j < 4; ++j) PROD(P[20 + j], buf[j]);
    } else {
        // border path (~3% of points, CTA-uniform): same streaming shape
        v12 = ldwin(fb, r, c, 12, q);               // center always in-bounds
        #pragma unroll
        for (int j = 0; j < 4; ++j) buf[j] = ldwin(fb, r, c, P[j], q);

        s_sh[2 * q]     = v12.x;
        s_sh[2 * q + 1] = v12.y;
        if (q < 25) {
            s_sh[256 + 2 * q]     = v12.x;
            s_sh[256 + 2 * q + 1] = v12.y;
        }
        __syncthreads();
        s0 = &s_sh[sb];

        #pragma unroll
        for (int bt = 0; bt < 5; ++bt) {
            #pragma unroll
            for (int j = 0; j < 4; ++j) {
                const float2 v = buf[j];
                buf[j] = ldwin(fb, r, c, P[4 * (bt + 1) + j], q);
                PROD(P[4 * bt + j], v);
            }
        }
        PROD(12, v12);
        #pragma unroll
        for (int j = 0; j < 4; ++j) PROD(P[20 + j], buf[j]);
    }

    pa[q] = a0;                          // plain STS — no atomics
    pb[q] = a1;
    __syncthreads();

    // ---- warp 0: static gather + softmax + expected offset ----
    if (q < 32) {
        const int lane = q;
        float logit = -INFINITY;
        if (lane < 25) {
            const int n  = lane;
            const int t0 = (256 * n + 49) / 50;     // first a0 contributor
            const int t1 = (256 * n + 255) / 50;    // last  a0 contributor
            float sum = (n > 0) ? pb[t0 - 1] : 0.0f;
            #pragma unroll 6
            for (int t = t0; t <= t1; ++t) sum += pa[t];   // 5-6 iters
            logit = sum;
        }
        float m = logit;
        #pragma unroll
        for (int o = 16; o > 0; o >>= 1)
            m = fmaxf(m, __shfl_xor_sync(0xffffffffu, m, o));
        float e = (lane < 25) ? __expf(logit - m) : 0.0f;
        float se = e;
        #pragma unroll
        for (int o = 16; o > 0; o >>= 1)
            se += __shfl_xor_sync(0xffffffffu, se, o);
        const float prb = e / se;        // 0 for lane >= 25

        // offsets: linspace(-3, 2, 5) = -3 + 1.25*k (exact fp32)
        const int ir = lane / 5;
        const int ic = lane - ir * 5;
        float dr = prb * (-3.0f + 1.25f * (float)ir);
        float dc = prb * (-3.0f + 1.25f * (float)ic);
        #pragma unroll
        for (int o = 16; o > 0; o >>= 1) {
            dr += __shfl_xor_sync(0xffffffffu, dr, o);
            dc += __shfl_xor_sync(0xffffffffu, dc, o);
        }
        if (lane == 0) {
            out[2 * pt + 0] = pr + dr;
            out[2 * pt + 1] = pc + dc;
        }
    }
}

extern "C" void kernel_launch(void* const* d_in, const int* in_sizes, int n_in,
                              void* d_out, int out_size)
{
    (void)in_sizes; (void)n_in; (void)out_size;
    // metadata order: 0=source_features (unused by reference), 1=target_features,
    // 2=coarse_positions, 3..6 = Wq,Wk,Wv,Wo (cancel algebraically)
    const float* tf  = (const float*)d_in[1];
    const float* pos = (const float*)d_in[2];
    float* out = (float*)d_out;

    fine_match_kernel<<<B_ * K_, 128>>>(tf, pos, out);
}

// round 16
// speedup vs baseline: 1.5690x; 1.1142x over previous
#include <cuda_runtime.h>
#include <math.h>

// FineMatchingModule — algebraically collapsed (verified R3-R15, rel_err ~1.5e-8):
// both attention layers add only window-uniform shifts which the final softmax
// cancels. Per point:
//   corr[n] = sum_j s[j] * flat[n*256+j],  n = 0..24
// flat[25*ch + p] = channel-major-flattened zero-padded 5x5 window of
// target_features at the truncated coarse position; s = center pixel channel
// vector (= pixel 12). refined = pos + softmax(corr) @ offsets,
// offsets1d = linspace(-3,2,5).
//
// R16 (FINAL, = R15 champion, 16.54us): bound by the random-window DRAM
// gather ceiling (~4.5TB/s) on the compulsory ~89MB unique footprint, which
// the traffic accounting shows is fully L2-deduplicated. Occupancy, barrier
// structure, buffer depth, CTA grain, access width, reduction style and
// pipelining were each varied independently across R4-R14; the floor is
// invariant. Configuration:
//   - 128-thread CTA = one point; ~10 CTAs/SM (launch_bounds(128,10), 48 reg).
//   - streaming 4-deep float2 register buffer: 6 consume-batches, each
//     issuing the next batch's 4 LDGs (load issue spread through compute).
//   - one staging barrier; dual-accumulator static-token reduction
//     (no atomics, no reduction shuffles); warp-0 gather + softmax (__expf).

#define B_ 4
#define K_ 1024
#define H_ 256
#define W_ 256
#define C_ 256

// float2-unit offset of pixel p from window base pointer
#define OFFP(p) (((p) / 5) * (W_ * (C_ / 2)) + ((p) % 5) * (C_ / 2))

// products of pixel p for this thread's channels: idx = 50q + p (x), +25 (y)
#define PROD(p, vv) do {                                            \
    const float sx_ = s0[(p)];                                      \
    const float sy_ = s0[25 + (p)];                                 \
    if ((p) < split)      a0 = fmaf((vv).x, sx_, a0);               \
    else                  a1 = fmaf((vv).x, sx_, a1);               \
    if ((p) + 25 < split) a0 = fmaf((vv).y, sy_, a0);               \
    else                  a1 = fmaf((vv).y, sy_, a1);               \
} while (0)

__device__ __forceinline__ float2 ldwin(const float* __restrict__ fb,
                                        int r, int c, int p, int q)
{
    const int rr = r - 2 + p / 5, cc = c - 2 + p % 5;
    if (rr >= 0 && rr < H_ && cc >= 0 && cc < W_)
        return ((const float2*)(fb + ((size_t)rr * W_ + cc) * C_))[q];
    return make_float2(0.f, 0.f);
}

__global__ __launch_bounds__(128, 10)
void fine_match_kernel(const float* __restrict__ tf,
                       const float* __restrict__ pos,
                       float* __restrict__ out)
{
    __shared__ float s_sh[312];          // center vector + 50-entry wrap
    __shared__ float pa[128];
    __shared__ float pb[128];

    const int q  = threadIdx.x;          // owns channels 2q, 2q+1
    const int pt = blockIdx.x;           // one point per CTA

    const float pr = pos[2 * pt + 0];
    const float pc = pos[2 * pt + 1];
    const int r = (int)pr, c = (int)pc;  // pos >= 0 -> trunc == astype(int32)
    const float* fb = tf + (size_t)(pt >> 10) * (H_ * W_ * C_);   // K = 1024

    const int sb    = (50 * q) & 255;
    const int split = 256 - sb;          // product index >= split -> token n0+1

    // pixel order excluding center (12): six batches of 4
    const int P[24] = { 0, 1, 2, 3,   4, 5, 6, 7,
                        8, 9,10,11,  13,14,15,16,
                       17,18,19,20,  21,22,23,24 };

    float a0 = 0.f, a1 = 0.f;
    const float* s0;
    float2 v12;
    float2 buf[4];

    const bool interior = (r >= 2) & (r <= H_ - 3) & (c >= 2) & (c <= W_ - 3);
    if (interior) {
        const float2* base =
            (const float2*)(fb + ((size_t)(r - 2) * W_ + (c - 2)) * C_) + q;
        v12 = base[OFFP(12)];                       // s source first
        #pragma unroll
        for (int j = 0; j < 4; ++j) buf[j] = base[OFFP(P[j])];

        s_sh[2 * q]     = v12.x;                    // stage s (+wrap)
        s_sh[2 * q + 1] = v12.y;
        if (q < 25) {
            s_sh[256 + 2 * q]     = v12.x;
            s_sh[256 + 2 * q + 1] = v12.y;
        }
        __syncthreads();
        s0 = &s_sh[sb];

        #pragma unroll
        for (int bt = 0; bt < 5; ++bt) {            // consume bt, load bt+1
            #pragma unroll
            for (int j = 0; j < 4; ++j) {
                const float2 v = buf[j];
                buf[j] = base[OFFP(P[4 * (bt + 1) + j])];
                PROD(P[4 * bt + j], v);
            }
        }
        PROD(12, v12);                              // center products
        #pragma unroll
        for (int j = 0; j < 4; ++j) PROD(P[20 + j], buf[j]);
    } else {
        // border path (~3% of points, CTA-uniform): same streaming shape
        v12 = ldwin(fb, r, c, 12, q);               // center always in-bounds
        #pragma unroll
        for (int j = 0; j < 4; ++j) buf[j] = ldwin(fb, r, c, P[j], q);

        s_sh[2 * q]     = v12.x;
        s_sh[2 * q + 1] = v12.y;
        if (q < 25) {
            s_sh[256 + 2 * q]     = v12.x;
            s_sh[256 + 2 * q + 1] = v12.y;
        }
        __syncthreads();
        s0 = &s_sh[sb];

        #pragma unroll
        for (int bt = 0; bt < 5; ++bt) {
            #pragma unroll
            for (int j = 0; j < 4; ++j) {
                const float2 v = buf[j];
                buf[j] = ldwin(fb, r, c, P[4 * (bt + 1) + j], q);
                PROD(P[4 * bt + j], v);
            }
        }
        PROD(12, v12);
        #pragma unroll
        for (int j = 0; j < 4; ++j) PROD(P[20 + j], buf[j]);
    }

    pa[q] = a0;                          // plain STS — no atomics
    pb[q] = a1;
    __syncthreads();

    // ---- warp 0: static gather + softmax + expected offset ----
    if (q < 32) {
        const int lane = q;
        float logit = -INFINITY;
        if (lane < 25) {
            const int n  = lane;
            const int t0 = (256 * n + 49) / 50;     // first a0 contributor
            const int t1 = (256 * n + 255) / 50;    // last  a0 contributor
            float sum = (n > 0) ? pb[t0 - 1] : 0.0f;
            #pragma unroll 6
            for (int t = t0; t <= t1; ++t) sum += pa[t];   // 5-6 iters
            logit = sum;
        }
        float m = logit;
        #pragma unroll
        for (int o = 16; o > 0; o >>= 1)
            m = fmaxf(m, __shfl_xor_sync(0xffffffffu, m, o));
        float e = (lane < 25) ? __expf(logit - m) : 0.0f;
        float se = e;
        #pragma unroll
        for (int o = 16; o > 0; o >>= 1)
            se += __shfl_xor_sync(0xffffffffu, se, o);
        const float prb = e / se;        // 0 for lane >= 25

        // offsets: linspace(-3, 2, 5) = -3 + 1.25*k (exact fp32)
        const int ir = lane / 5;
        const int ic = lane - ir * 5;
        float dr = prb * (-3.0f + 1.25f * (float)ir);
        float dc = prb * (-3.0f + 1.25f * (float)ic);
        #pragma unroll
        for (int o = 16; o > 0; o >>= 1) {
            dr += __shfl_xor_sync(0xffffffffu, dr, o);
            dc += __shfl_xor_sync(0xffffffffu, dc, o);
        }
        if (lane == 0) {
            out[2 * pt + 0] = pr + dr;
            out[2 * pt + 1] = pc + dc;
        }
    }
}

extern "C" void kernel_launch(void* const* d_in, const int* in_sizes, int n_in,
                              void* d_out, int out_size)
{
    (void)in_sizes; (void)n_in; (void)out_size;
    // metadata order: 0=source_features (unused by reference), 1=target_features,
    // 2=coarse_positions, 3..6 = Wq,Wk,Wv,Wo (cancel algebraically)
    const float* tf  = (const float*)d_in[1];
    const float* pos = (const float*)d_in[2];
    float* out = (float*)d_out;

    fine_match_kernel<<<B_ * K_, 128>>>(tf, pos, out);
}